// round 7
// baseline (speedup 1.0000x reference)
#include <cuda_runtime.h>

#define HW     4096
#define WIDTH  64
#define CDIM   256
#define NH     8
#define HD     32
#define BATCH  2
#define SCALE  0.17677669529663687f

// Scratch (device globals; no allocation allowed)
__device__ float g_q[BATCH * NH * HW * HD];      // [b, head, p, d]
__device__ float g_k[BATCH * NH * HW * HD];      // [b, head, p, d]
__device__ float g_v[BATCH * NH * HW * HD];      // [b, head, p, d]
__device__ float g_attn[BATCH * HW * CDIM];      // [b, p, c]  c = head*32+d

// ---------------------------------------------------------------------------
// tf32 MMA helpers
// ---------------------------------------------------------------------------
__device__ __forceinline__ unsigned f2tf(float f)
{
    unsigned u;
    asm("cvt.rna.tf32.f32 %0, %1;" : "=r"(u) : "f"(f));
    return u;
}

__device__ __forceinline__ void mma8(float d[4], const unsigned a[4], const unsigned b[2])
{
    asm("mma.sync.aligned.m16n8k8.row.col.f32.tf32.tf32.f32 "
        "{%0,%1,%2,%3}, {%4,%5,%6,%7}, {%8,%9}, {%0,%1,%2,%3};"
        : "+f"(d[0]), "+f"(d[1]), "+f"(d[2]), "+f"(d[3])
        : "r"(a[0]), "r"(a[1]), "r"(a[2]), "r"(a[3]),
          "r"(b[0]), "r"(b[1]));
}

// ---------------------------------------------------------------------------
// Kernel 1: QKV projection, tf32, double-buffered. Tile 64(M) x 128(N),
// k-chunk 32, 8 warps (2x4), warp tile 32x32 (2x4 mma tiles).
// ---------------------------------------------------------------------------
__global__ __launch_bounds__(256) void qkv_gemm_kernel(
    const float* __restrict__ x,
    const float* __restrict__ w0, const float* __restrict__ bb0,
    const float* __restrict__ w1, const float* __restrict__ bb1,
    const float* __restrict__ w2, const float* __restrict__ bb2)
{
    __shared__ unsigned As[2][64][36];     // [m][k] tf32
    __shared__ unsigned Bs[2][32][136];    // [k][n] tf32
    __shared__ const float* Arow[64];
    __shared__ float* rowDst[64];
    __shared__ float biasS[64];

    const int tid  = threadIdx.x;
    const int row0 = blockIdx.y * 64;
    const int col0 = blockIdx.x * 128;
    const int b    = blockIdx.z;

    if (tid < 64) {
        int M = row0 + tid;
        int t = M >> 8;
        int rem = M & 255;
        int head = rem >> 5, d = rem & 31;
        const float* w; const float* bb;
        if (head < 4)      { w = w0; bb = bb0; }
        else if (head < 7) { w = w1; bb = bb1; }
        else               { w = w2; bb = bb2; }
        Arow[tid]  = w + (size_t)(t * 256 + rem) * 256;
        biasS[tid] = bb[t * 256 + rem];
        float* dst = (t == 0) ? g_q : (t == 1) ? g_k : g_v;
        rowDst[tid] = dst + ((size_t)(b * NH + head) * HW) * HD + d;
    }
    __syncthreads();

    const int wid  = tid >> 5;
    const int lane = tid & 31;
    const int g = lane >> 2, t4 = lane & 3;
    const int m0 = (wid >> 2) * 32;            // 0 / 32
    const int n0 = (wid & 3) * 32;             // 0 / 32 / 64 / 96

    const int am = tid >> 2, ak = (tid & 3) * 8;   // A loader: 64x32
    const int bk = tid >> 3, bn = (tid & 7) * 16;  // B loader: 32x128

    const float* xb = x + (size_t)b * CDIM * HW;
    float acc[2][4][4] = {};

    float4 aR0, aR1, bR0, bR1, bR2, bR3;

    // prefetch chunk 0
    {
        const float* s = Arow[am] + ak;
        aR0 = *(const float4*)s; aR1 = *(const float4*)(s + 4);
        const float* sb = xb + (size_t)bk * HW + col0 + bn;
        bR0 = *(const float4*)sb;      bR1 = *(const float4*)(sb + 4);
        bR2 = *(const float4*)(sb + 8); bR3 = *(const float4*)(sb + 12);
    }
    {
        unsigned* a = &As[0][am][ak];
        a[0] = f2tf(aR0.x); a[1] = f2tf(aR0.y); a[2] = f2tf(aR0.z); a[3] = f2tf(aR0.w);
        a[4] = f2tf(aR1.x); a[5] = f2tf(aR1.y); a[6] = f2tf(aR1.z); a[7] = f2tf(aR1.w);
        unsigned* bs = &Bs[0][bk][bn];
        bs[0]  = f2tf(bR0.x); bs[1]  = f2tf(bR0.y); bs[2]  = f2tf(bR0.z); bs[3]  = f2tf(bR0.w);
        bs[4]  = f2tf(bR1.x); bs[5]  = f2tf(bR1.y); bs[6]  = f2tf(bR1.z); bs[7]  = f2tf(bR1.w);
        bs[8]  = f2tf(bR2.x); bs[9]  = f2tf(bR2.y); bs[10] = f2tf(bR2.z); bs[11] = f2tf(bR2.w);
        bs[12] = f2tf(bR3.x); bs[13] = f2tf(bR3.y); bs[14] = f2tf(bR3.z); bs[15] = f2tf(bR3.w);
    }
    __syncthreads();

    for (int i = 0; i < 8; i++) {
        const int cur = i & 1;
        if (i < 7) {
            const int k1 = (i + 1) * 32;
            const float* s = Arow[am] + k1 + ak;
            aR0 = *(const float4*)s; aR1 = *(const float4*)(s + 4);
            const float* sb = xb + (size_t)(k1 + bk) * HW + col0 + bn;
            bR0 = *(const float4*)sb;      bR1 = *(const float4*)(sb + 4);
            bR2 = *(const float4*)(sb + 8); bR3 = *(const float4*)(sb + 12);
        }
        #pragma unroll
        for (int ks = 0; ks < 4; ks++) {
            const int kk = ks * 8;
            unsigned a[2][4], bf[4][2];
            #pragma unroll
            for (int mi = 0; mi < 2; mi++) {
                const int mr = m0 + mi * 16;
                a[mi][0] = As[cur][mr + g][kk + t4];
                a[mi][1] = As[cur][mr + g + 8][kk + t4];
                a[mi][2] = As[cur][mr + g][kk + t4 + 4];
                a[mi][3] = As[cur][mr + g + 8][kk + t4 + 4];
            }
            #pragma unroll
            for (int ni = 0; ni < 4; ni++) {
                const int nc = n0 + ni * 8 + g;
                bf[ni][0] = Bs[cur][kk + t4][nc];
                bf[ni][1] = Bs[cur][kk + t4 + 4][nc];
            }
            #pragma unroll
            for (int mi = 0; mi < 2; mi++)
                #pragma unroll
                for (int ni = 0; ni < 4; ni++)
                    mma8(acc[mi][ni], a[mi], bf[ni]);
        }
        if (i < 7) {
            const int nxt = 1 - cur;
            unsigned* a = &As[nxt][am][ak];
            a[0] = f2tf(aR0.x); a[1] = f2tf(aR0.y); a[2] = f2tf(aR0.z); a[3] = f2tf(aR0.w);
            a[4] = f2tf(aR1.x); a[5] = f2tf(aR1.y); a[6] = f2tf(aR1.z); a[7] = f2tf(aR1.w);
            unsigned* bs = &Bs[nxt][bk][bn];
            bs[0]  = f2tf(bR0.x); bs[1]  = f2tf(bR0.y); bs[2]  = f2tf(bR0.z); bs[3]  = f2tf(bR0.w);
            bs[4]  = f2tf(bR1.x); bs[5]  = f2tf(bR1.y); bs[6]  = f2tf(bR1.z); bs[7]  = f2tf(bR1.w);
            bs[8]  = f2tf(bR2.x); bs[9]  = f2tf(bR2.y); bs[10] = f2tf(bR2.z); bs[11] = f2tf(bR2.w);
            bs[12] = f2tf(bR3.x); bs[13] = f2tf(bR3.y); bs[14] = f2tf(bR3.z); bs[15] = f2tf(bR3.w);
            __syncthreads();
        }
    }

    #pragma unroll
    for (int mi = 0; mi < 2; mi++) {
        const int rl = m0 + mi * 16 + g;
        const int rh = rl + 8;
        float* dl = rowDst[rl]; const float bl = biasS[rl];
        float* dh = rowDst[rh]; const float bh = biasS[rh];
        #pragma unroll
        for (int ni = 0; ni < 4; ni++) {
            const int p = col0 + n0 + ni * 8 + 2 * t4;
            dl[(size_t)p * HD]       = acc[mi][ni][0] + bl;
            dl[(size_t)(p + 1) * HD] = acc[mi][ni][1] + bl;
            dh[(size_t)p * HD]       = acc[mi][ni][2] + bh;
            dh[(size_t)(p + 1) * HD] = acc[mi][ni][3] + bh;
        }
    }
}

// ---------------------------------------------------------------------------
// Kernel 2: neighborhood attention (proven R6 version). One warp per
// (b, head, pixel); lane = d. Interior pixels: compile-time neighbor offsets.
// Border: general path; OOB neighbors keep logit = 0 inside the softmax.
// ---------------------------------------------------------------------------
template <int KSZ, int DIL, bool INTERIOR>
__device__ __forceinline__ void attn_body(int lane, int b, int head, int p)
{
    constexpr int L = KSZ * KSZ;
    constexpr int NL = (L + 31) / 32;
    constexpr int HALF = KSZ / 2;

    const int y = p >> 6, x = p & 63;
    const int hb = ((b * NH + head) * HW) * HD;
    const float* __restrict__ kb = g_k + hb;
    const float* __restrict__ vb = g_v + hb;

    const float q = g_q[hb + p * HD + lane] * SCALE;

    float lgs[NL];
    if (INTERIOR) {
        const float* __restrict__ kp = kb + p * HD + lane;
        #pragma unroll
        for (int batch = 0; batch < NL; batch++) {
            float v[32];
            #pragma unroll
            for (int j = 0; j < 32; j++) {
                const int idx = batch * 32 + j;
                if (idx < L) {
                    const int off = ((idx / KSZ - HALF) * DIL * 64
                                   + (idx % KSZ - HALF) * DIL) * HD;
                    v[j] = q * kp[off];
                } else {
                    v[j] = 0.f;
                }
            }
            #pragma unroll
            for (int m = 16; m >= 1; m >>= 1) {
                const bool up = (lane & m) != 0;
                #pragma unroll
                for (int j = 0; j < m; j++) {
                    float send = up ? v[j] : v[j + m];
                    float recv = __shfl_xor_sync(0xffffffffu, send, m);
                    v[j] = (up ? v[j + m] : v[j]) + recv;
                }
            }
            lgs[batch] = v[0];
        }
    } else {
        #pragma unroll
        for (int batch = 0; batch < NL; batch++) {
            float v[32];
            #pragma unroll
            for (int j = 0; j < 32; j++) {
                const int idx = batch * 32 + j;
                float kval = 0.f;
                if (idx < L) {
                    const int ky = idx / KSZ, kx = idx % KSZ;
                    const int ny = y + (ky - HALF) * DIL;
                    const int nx = x + (kx - HALF) * DIL;
                    if ((unsigned)ny < 64u && (unsigned)nx < 64u)
                        kval = kb[(ny * 64 + nx) * HD + lane];
                }
                v[j] = q * kval;
            }
            #pragma unroll
            for (int m = 16; m >= 1; m >>= 1) {
                const bool up = (lane & m) != 0;
                #pragma unroll
                for (int j = 0; j < m; j++) {
                    float send = up ? v[j] : v[j + m];
                    float recv = __shfl_xor_sync(0xffffffffu, send, m);
                    v[j] = (up ? v[j + m] : v[j]) + recv;
                }
            }
            lgs[batch] = v[0];
        }
    }

    float mx = -1e30f;
    #pragma unroll
    for (int j = 0; j < NL; j++)
        if (j * 32 + lane < L) mx = fmaxf(mx, lgs[j]);
    #pragma unroll
    for (int o = 16; o > 0; o >>= 1)
        mx = fmaxf(mx, __shfl_xor_sync(0xffffffffu, mx, o));

    float e[NL];
    float sum = 0.f;
    #pragma unroll
    for (int j = 0; j < NL; j++) {
        e[j] = (j * 32 + lane < L) ? __expf(lgs[j] - mx) : 0.f;
        sum += e[j];
    }
    #pragma unroll
    for (int o = 16; o > 0; o >>= 1)
        sum += __shfl_xor_sync(0xffffffffu, sum, o);
    const float inv = 1.f / sum;

    float acc = 0.f;
    if (INTERIOR) {
        const float* __restrict__ vp = vb + p * HD + lane;
        #pragma unroll
        for (int l = 0; l < L; l++) {
            const int off = ((l / KSZ - HALF) * DIL * 64
                           + (l % KSZ - HALF) * DIL) * HD;
            float pl = __shfl_sync(0xffffffffu, e[l >> 5], l & 31) * inv;
            acc += pl * vp[off];
        }
    } else {
        #pragma unroll
        for (int ky = 0; ky < KSZ; ky++) {
            const int ny = y + (ky - HALF) * DIL;
            #pragma unroll
            for (int kx = 0; kx < KSZ; kx++) {
                const int l = ky * KSZ + kx;
                const int nx = x + (kx - HALF) * DIL;
                if ((unsigned)ny < 64u && (unsigned)nx < 64u) {
                    float pl = __shfl_sync(0xffffffffu, e[l >> 5], l & 31) * inv;
                    acc += pl * vb[(ny * 64 + nx) * HD + lane];
                }
            }
        }
    }

    g_attn[(b * HW + p) * CDIM + head * HD + lane] = acc;
}

template <int KSZ, int DIL>
__device__ __forceinline__ void attn_dispatch(int lane, int b, int head, int p)
{
    constexpr int R = (KSZ / 2) * DIL;
    const int y = p >> 6, x = p & 63;
    if (y >= R && y < 64 - R && x >= R && x < 64 - R)
        attn_body<KSZ, DIL, true>(lane, b, head, p);
    else
        attn_body<KSZ, DIL, false>(lane, b, head, p);
}

__global__ __launch_bounds__(256) void attn_kernel()
{
    const int lane = threadIdx.x & 31;
    const int wid  = threadIdx.x >> 5;
    const int W    = blockIdx.x * 8 + wid;
    const int p    = W & (HW - 1);
    const int head = (W >> 12) & 7;
    const int b    = W >> 15;

    if (head < 4)      attn_dispatch<5, 1>(lane, b, head, p);
    else if (head < 7) attn_dispatch<7, 2>(lane, b, head, p);
    else               attn_dispatch<9, 3>(lane, b, head, p);
}

// ---------------------------------------------------------------------------
// Kernel 3: output projection, tf32, double-buffered. Tile 64x64.
// attn[p][c] is natively col-major ([n][k]) for mma.row.col.
// ---------------------------------------------------------------------------
__global__ __launch_bounds__(256) void proj_gemm_kernel(
    const float* __restrict__ pw, const float* __restrict__ pb,
    float* __restrict__ out)
{
    __shared__ unsigned As[2][64][36];     // [m][k] tf32
    __shared__ unsigned Bs[2][64][36];     // [n][k] tf32

    const int tid  = threadIdx.x;
    const int row0 = blockIdx.y * 64;
    const int col0 = blockIdx.x * 64;
    const int b    = blockIdx.z;

    const int wid  = tid >> 5;
    const int lane = tid & 31;
    const int g = lane >> 2, t4 = lane & 3;
    const int m0 = (wid >> 2) * 32;
    const int n0 = (wid & 3) * 16;

    const int am = tid >> 2, ak = (tid & 3) * 8;

    const float* attb = g_attn + (size_t)b * HW * CDIM;
    const float* apw  = pw + (size_t)(row0 + am) * 256 + ak;
    const float* abb  = attb + (size_t)(col0 + am) * CDIM + ak;

    float acc[2][2][4] = {};
    float4 aR0, aR1, bR0, bR1;

    aR0 = *(const float4*)apw; aR1 = *(const float4*)(apw + 4);
    bR0 = *(const float4*)abb; bR1 = *(const float4*)(abb + 4);
    {
        unsigned* a = &As[0][am][ak];
        a[0] = f2tf(aR0.x); a[1] = f2tf(aR0.y); a[2] = f2tf(aR0.z); a[3] = f2tf(aR0.w);
        a[4] = f2tf(aR1.x); a[5] = f2tf(aR1.y); a[6] = f2tf(aR1.z); a[7] = f2tf(aR1.w);
        unsigned* bs = &Bs[0][am][ak];
        bs[0] = f2tf(bR0.x); bs[1] = f2tf(bR0.y); bs[2] = f2tf(bR0.z); bs[3] = f2tf(bR0.w);
        bs[4] = f2tf(bR1.x); bs[5] = f2tf(bR1.y); bs[6] = f2tf(bR1.z); bs[7] = f2tf(bR1.w);
    }
    __syncthreads();

    for (int i = 0; i < 8; i++) {
        const int cur = i & 1;
        if (i < 7) {
            const int k1 = (i + 1) * 32;
            aR0 = *(const float4*)(apw + k1); aR1 = *(const float4*)(apw + k1 + 4);
            bR0 = *(const float4*)(abb + k1); bR1 = *(const float4*)(abb + k1 + 4);
        }
        #pragma unroll
        for (int ks = 0; ks < 4; ks++) {
            const int kk = ks * 8;
            unsigned a[2][4], bf[2][2];
            #pragma unroll
            for (int mi = 0; mi < 2; mi++) {
                const int mr = m0 + mi * 16;
                a[mi][0] = As[cur][mr + g][kk + t4];
                a[mi][1] = As[cur][mr + g + 8][kk + t4];
                a[mi][2] = As[cur][mr + g][kk + t4 + 4];
                a[mi][3] = As[cur][mr + g + 8][kk + t4 + 4];
            }
            #pragma unroll
            for (int ni = 0; ni < 2; ni++) {
                const int nc = n0 + ni * 8 + g;
                bf[ni][0] = Bs[cur][nc][kk + t4];
                bf[ni][1] = Bs[cur][nc][kk + t4 + 4];
            }
            #pragma unroll
            for (int mi = 0; mi < 2; mi++)
                #pragma unroll
                for (int ni = 0; ni < 2; ni++)
                    mma8(acc[mi][ni], a[mi], bf[ni]);
        }
        if (i < 7) {
            const int nxt = 1 - cur;
            unsigned* a = &As[nxt][am][ak];
            a[0] = f2tf(aR0.x); a[1] = f2tf(aR0.y); a[2] = f2tf(aR0.z); a[3] = f2tf(aR0.w);
            a[4] = f2tf(aR1.x); a[5] = f2tf(aR1.y); a[6] = f2tf(aR1.z); a[7] = f2tf(aR1.w);
            unsigned* bs = &Bs[nxt][am][ak];
            bs[0] = f2tf(bR0.x); bs[1] = f2tf(bR0.y); bs[2] = f2tf(bR0.z); bs[3] = f2tf(bR0.w);
            bs[4] = f2tf(bR1.x); bs[5] = f2tf(bR1.y); bs[6] = f2tf(bR1.z); bs[7] = f2tf(bR1.w);
            __syncthreads();
        }
    }

    #pragma unroll
    for (int mi = 0; mi < 2; mi++) {
        const int ol = row0 + m0 + mi * 16 + g;
        const int oh = ol + 8;
        const float bl = pb[ol], bh = pb[oh];
        float* basel = out + ((size_t)b * CDIM + ol) * HW;
        float* baseh = out + ((size_t)b * CDIM + oh) * HW;
        #pragma unroll
        for (int ni = 0; ni < 2; ni++) {
            const int p = col0 + n0 + ni * 8 + 2 * t4;
            *(float2*)(basel + p) =
                make_float2(acc[mi][ni][0] + bl, acc[mi][ni][1] + bl);
            *(float2*)(baseh + p) =
                make_float2(acc[mi][ni][2] + bh, acc[mi][ni][3] + bh);
        }
    }
}

// ---------------------------------------------------------------------------
extern "C" void kernel_launch(void* const* d_in, const int* in_sizes, int n_in,
                              void* d_out, int out_size)
{
    const float* x   = (const float*)d_in[0];
    const float* w0  = (const float*)d_in[1];
    const float* bb0 = (const float*)d_in[2];
    const float* w1  = (const float*)d_in[3];
    const float* bb1 = (const float*)d_in[4];
    const float* w2  = (const float*)d_in[5];
    const float* bb2 = (const float*)d_in[6];
    const float* pw  = (const float*)d_in[7];
    const float* pb  = (const float*)d_in[8];
    float* out = (float*)d_out;

    qkv_gemm_kernel<<<dim3(HW / 128, 768 / 64, BATCH), 256>>>(
        x, w0, bb0, w1, bb1, w2, bb2);

    attn_kernel<<<(BATCH * NH * HW) / 8, 256>>>();

    proj_gemm_kernel<<<dim3(HW / 64, CDIM / 64, BATCH), 256>>>(pw, pb, out);
}

// round 8
// speedup vs baseline: 1.3700x; 1.3700x over previous
#include <cuda_runtime.h>

#define HW     4096
#define WIDTH  64
#define CDIM   256
#define NH     8
#define HD     32
#define BATCH  2
#define SCALE  0.17677669529663687f

// Scratch (device globals; no allocation allowed)
__device__ float g_q[BATCH * NH * HW * HD];      // [b, head, p, d]
__device__ float g_k[BATCH * NH * HW * HD];      // [b, head, p, d]
__device__ float g_v[BATCH * NH * HW * HD];      // [b, head, p, d]
__device__ float g_attn[BATCH * HW * CDIM];      // [b, p, c]  c = head*32+d

// ---------------------------------------------------------------------------
// tf32 MMA helpers
// ---------------------------------------------------------------------------
__device__ __forceinline__ unsigned f2tf(float f)
{
    unsigned u;
    asm("cvt.rna.tf32.f32 %0, %1;" : "=r"(u) : "f"(f));
    return u;
}

__device__ __forceinline__ void mma8(float d[4], const unsigned a[4], const unsigned b[2])
{
    asm("mma.sync.aligned.m16n8k8.row.col.f32.tf32.tf32.f32 "
        "{%0,%1,%2,%3}, {%4,%5,%6,%7}, {%8,%9}, {%0,%1,%2,%3};"
        : "+f"(d[0]), "+f"(d[1]), "+f"(d[2]), "+f"(d[3])
        : "r"(a[0]), "r"(a[1]), "r"(a[2]), "r"(a[3]),
          "r"(b[0]), "r"(b[1]));
}

// ---------------------------------------------------------------------------
// Kernel 1: QKV projection, tf32 tensor-core (proven R5/R6 version).
// ---------------------------------------------------------------------------
__global__ __launch_bounds__(256) void qkv_gemm_kernel(
    const float* __restrict__ x,
    const float* __restrict__ w0, const float* __restrict__ bb0,
    const float* __restrict__ w1, const float* __restrict__ bb1,
    const float* __restrict__ w2, const float* __restrict__ bb2)
{
    __shared__ unsigned As[64][36];
    __shared__ unsigned Bs[32][72];
    __shared__ const float* Arow[64];
    __shared__ float* rowDst[64];
    __shared__ float biasS[64];

    const int tid  = threadIdx.x;
    const int row0 = blockIdx.y * 64;
    const int col0 = blockIdx.x * 64;
    const int b    = blockIdx.z;

    if (tid < 64) {
        int M = row0 + tid;
        int t = M >> 8;
        int rem = M & 255;
        int head = rem >> 5, d = rem & 31;
        const float* w; const float* bb;
        if (head < 4)      { w = w0; bb = bb0; }
        else if (head < 7) { w = w1; bb = bb1; }
        else               { w = w2; bb = bb2; }
        Arow[tid]  = w + (size_t)(t * 256 + rem) * 256;
        biasS[tid] = bb[t * 256 + rem];
        float* dst = (t == 0) ? g_q : (t == 1) ? g_k : g_v;
        rowDst[tid] = dst + ((size_t)(b * NH + head) * HW) * HD + d;
    }
    __syncthreads();

    const int wid  = tid >> 5;
    const int lane = tid & 31;
    const int g = lane >> 2, t4 = lane & 3;
    const int m0 = (wid >> 2) * 32;
    const int n0 = (wid & 3) * 16;

    const int am = tid >> 2, ak = (tid & 3) * 8;
    const int bk = tid >> 3, bn = (tid & 7) * 8;

    const float* xb = x + (size_t)b * CDIM * HW;
    float acc[2][2][4] = {};

    for (int k0 = 0; k0 < 256; k0 += 32) {
        {
            const float* src = Arow[am] + k0 + ak;
            float4 v0 = *(const float4*)(src);
            float4 v1 = *(const float4*)(src + 4);
            As[am][ak + 0] = f2tf(v0.x); As[am][ak + 1] = f2tf(v0.y);
            As[am][ak + 2] = f2tf(v0.z); As[am][ak + 3] = f2tf(v0.w);
            As[am][ak + 4] = f2tf(v1.x); As[am][ak + 5] = f2tf(v1.y);
            As[am][ak + 6] = f2tf(v1.z); As[am][ak + 7] = f2tf(v1.w);
        }
        {
            const float* src = xb + (size_t)(k0 + bk) * HW + col0 + bn;
            float4 v0 = *(const float4*)(src);
            float4 v1 = *(const float4*)(src + 4);
            Bs[bk][bn + 0] = f2tf(v0.x); Bs[bk][bn + 1] = f2tf(v0.y);
            Bs[bk][bn + 2] = f2tf(v0.z); Bs[bk][bn + 3] = f2tf(v0.w);
            Bs[bk][bn + 4] = f2tf(v1.x); Bs[bk][bn + 5] = f2tf(v1.y);
            Bs[bk][bn + 6] = f2tf(v1.z); Bs[bk][bn + 7] = f2tf(v1.w);
        }
        __syncthreads();
        #pragma unroll
        for (int ks = 0; ks < 4; ks++) {
            const int kk = ks * 8;
            unsigned a[2][4], bf[2][2];
            #pragma unroll
            for (int mi = 0; mi < 2; mi++) {
                const int mr = m0 + mi * 16;
                a[mi][0] = As[mr + g][kk + t4];
                a[mi][1] = As[mr + g + 8][kk + t4];
                a[mi][2] = As[mr + g][kk + t4 + 4];
                a[mi][3] = As[mr + g + 8][kk + t4 + 4];
            }
            #pragma unroll
            for (int ni = 0; ni < 2; ni++) {
                const int nc = n0 + ni * 8 + g;
                bf[ni][0] = Bs[kk + t4][nc];
                bf[ni][1] = Bs[kk + t4 + 4][nc];
            }
            #pragma unroll
            for (int mi = 0; mi < 2; mi++)
                #pragma unroll
                for (int ni = 0; ni < 2; ni++)
                    mma8(acc[mi][ni], a[mi], bf[ni]);
        }
        __syncthreads();
    }

    #pragma unroll
    for (int mi = 0; mi < 2; mi++) {
        const int rl = m0 + mi * 16 + g;
        const int rh = rl + 8;
        float* dl = rowDst[rl]; const float bl = biasS[rl];
        float* dh = rowDst[rh]; const float bh = biasS[rh];
        #pragma unroll
        for (int ni = 0; ni < 2; ni++) {
            const int p = col0 + n0 + ni * 8 + 2 * t4;
            dl[(size_t)p * HD]       = acc[mi][ni][0] + bl;
            dl[(size_t)(p + 1) * HD] = acc[mi][ni][1] + bl;
            dh[(size_t)p * HD]       = acc[mi][ni][2] + bh;
            dh[(size_t)(p + 1) * HD] = acc[mi][ni][3] + bh;
        }
    }
}

// ---------------------------------------------------------------------------
// Kernel 2: neighborhood attention, quad-pixel warps. One warp = 4 adjacent
// pixels in a row; 8 lanes per pixel; each lane holds 4 dims (float4).
// Per neighbor: one coalesced LDG.128 serves all 4 pixels; logit = 8-lane
// reduction (3 shfl_xor). Logits stored lane-sliced: slot j on lane r holds
// neighbor n = j*8+r. Invalid slots stay -1e30 -> exp = 0. OOB neighbors
// (border path) keep logit = 0 inside the softmax (F.unfold zero padding).
// ---------------------------------------------------------------------------
template <int KSZ, int DIL, bool INTERIOR>
__device__ __forceinline__ void attn_quad(int lane, int b, int head, int p0)
{
    constexpr int L = KSZ * KSZ;
    constexpr int NL8 = (L + 7) / 8;
    constexpr int HALF = KSZ / 2;

    const int r = lane & 7;           // dim group: d = 4r..4r+3
    const int g = lane >> 3;          // pixel within quad
    const int p = p0 + g;
    const int y = p0 >> 6;
    const int x = (p0 & 63) + g;

    const int hb = ((b * NH + head) * HW) * HD;
    const float* __restrict__ kb = g_k + hb;
    const float* __restrict__ vb = g_v + hb;
    const int lo = p * HD + r * 4;    // lane offset within head-plane

    float4 qv = *(const float4*)(g_q + hb + lo);
    qv.x *= SCALE; qv.y *= SCALE; qv.z *= SCALE; qv.w *= SCALE;

    float lgs[NL8];
    #pragma unroll
    for (int j = 0; j < NL8; j++) lgs[j] = -1e30f;

    const float* __restrict__ kp = kb + lo;

    #pragma unroll
    for (int n = 0; n < L; n++) {
        const int dy = n / KSZ - HALF, dx = n % KSZ - HALF;
        float4 kv;
        if (INTERIOR) {
            kv = *(const float4*)(kp + (dy * 64 + dx) * DIL * HD);
        } else {
            const int ny = y + dy * DIL;
            const int nx = x + dx * DIL;
            if ((unsigned)ny < 64u && (unsigned)nx < 64u)
                kv = *(const float4*)(kb + (ny * 64 + nx) * HD + r * 4);
            else
                kv = make_float4(0.f, 0.f, 0.f, 0.f);
        }
        float s = qv.x * kv.x + qv.y * kv.y + qv.z * kv.z + qv.w * kv.w;
        s += __shfl_xor_sync(0xffffffffu, s, 4);
        s += __shfl_xor_sync(0xffffffffu, s, 2);
        s += __shfl_xor_sync(0xffffffffu, s, 1);
        if (r == (n & 7)) lgs[n >> 3] = s;
    }

    // Softmax per pixel: reduce across NL8 regs x 8 lanes of the group.
    float mx = lgs[0];
    #pragma unroll
    for (int j = 1; j < NL8; j++) mx = fmaxf(mx, lgs[j]);
    mx = fmaxf(mx, __shfl_xor_sync(0xffffffffu, mx, 4));
    mx = fmaxf(mx, __shfl_xor_sync(0xffffffffu, mx, 2));
    mx = fmaxf(mx, __shfl_xor_sync(0xffffffffu, mx, 1));

    float e[NL8];
    float sum = 0.f;
    #pragma unroll
    for (int j = 0; j < NL8; j++) {
        e[j] = __expf(lgs[j] - mx);       // invalid slots -> exp(-huge) = 0
        sum += e[j];
    }
    sum += __shfl_xor_sync(0xffffffffu, sum, 4);
    sum += __shfl_xor_sync(0xffffffffu, sum, 2);
    sum += __shfl_xor_sync(0xffffffffu, sum, 1);
    const float inv = 1.f / sum;
    #pragma unroll
    for (int j = 0; j < NL8; j++) e[j] *= inv;

    // PV phase
    const int gbase = lane & 24;          // first lane of this pixel group
    const float* __restrict__ vp = vb + lo;
    float4 acc = make_float4(0.f, 0.f, 0.f, 0.f);

    #pragma unroll
    for (int n = 0; n < L; n++) {
        const int dy = n / KSZ - HALF, dx = n % KSZ - HALF;
        const float w = __shfl_sync(0xffffffffu, e[n >> 3], gbase + (n & 7));
        if (INTERIOR) {
            float4 vv = *(const float4*)(vp + (dy * 64 + dx) * DIL * HD);
            acc.x += w * vv.x; acc.y += w * vv.y;
            acc.z += w * vv.z; acc.w += w * vv.w;
        } else {
            const int ny = y + dy * DIL;
            const int nx = x + dx * DIL;
            if ((unsigned)ny < 64u && (unsigned)nx < 64u) {
                float4 vv = *(const float4*)(vb + (ny * 64 + nx) * HD + r * 4);
                acc.x += w * vv.x; acc.y += w * vv.y;
                acc.z += w * vv.z; acc.w += w * vv.w;
            }
        }
    }

    *(float4*)(g_attn + ((size_t)(b * HW + p)) * CDIM + head * HD + r * 4) = acc;
}

template <int KSZ, int DIL>
__device__ __forceinline__ void attn_quad_dispatch(int lane, int b, int head, int p0)
{
    constexpr int R = (KSZ / 2) * DIL;
    const int y = p0 >> 6, x0 = p0 & 63;
    if (y >= R && y < 64 - R && x0 >= R && x0 + 3 < 64 - R)
        attn_quad<KSZ, DIL, true>(lane, b, head, p0);
    else
        attn_quad<KSZ, DIL, false>(lane, b, head, p0);
}

__global__ __launch_bounds__(256) void attn_kernel()
{
    const int lane = threadIdx.x & 31;
    const int wid  = threadIdx.x >> 5;
    const int W    = blockIdx.x * 8 + wid;       // quad index over B*NH*HW/4
    const int p0   = (W & 1023) * 4;
    const int head = (W >> 10) & 7;
    const int b    = W >> 13;

    if (head < 4)      attn_quad_dispatch<5, 1>(lane, b, head, p0);
    else if (head < 7) attn_quad_dispatch<7, 2>(lane, b, head, p0);
    else               attn_quad_dispatch<9, 3>(lane, b, head, p0);
}

// ---------------------------------------------------------------------------
// Kernel 3: output projection, tf32 tensor-core (proven R5/R6 version).
// ---------------------------------------------------------------------------
__global__ __launch_bounds__(256) void proj_gemm_kernel(
    const float* __restrict__ pw, const float* __restrict__ pb,
    float* __restrict__ out)
{
    __shared__ unsigned As[64][36];
    __shared__ unsigned Bs[64][36];

    const int tid  = threadIdx.x;
    const int row0 = blockIdx.y * 64;
    const int col0 = blockIdx.x * 64;
    const int b    = blockIdx.z;

    const int wid  = tid >> 5;
    const int lane = tid & 31;
    const int g = lane >> 2, t4 = lane & 3;
    const int m0 = (wid >> 2) * 32;
    const int n0 = (wid & 3) * 16;

    const int am = tid >> 2, ak = (tid & 3) * 8;

    const float* attb = g_attn + (size_t)b * HW * CDIM;
    float acc[2][2][4] = {};

    for (int k0 = 0; k0 < 256; k0 += 32) {
        {
            const float* src = pw + (size_t)(row0 + am) * 256 + k0 + ak;
            float4 v0 = *(const float4*)(src);
            float4 v1 = *(const float4*)(src + 4);
            As[am][ak + 0] = f2tf(v0.x); As[am][ak + 1] = f2tf(v0.y);
            As[am][ak + 2] = f2tf(v0.z); As[am][ak + 3] = f2tf(v0.w);
            As[am][ak + 4] = f2tf(v1.x); As[am][ak + 5] = f2tf(v1.y);
            As[am][ak + 6] = f2tf(v1.z); As[am][ak + 7] = f2tf(v1.w);
        }
        {
            const float* src = attb + (size_t)(col0 + am) * CDIM + k0 + ak;
            float4 v0 = *(const float4*)(src);
            float4 v1 = *(const float4*)(src + 4);
            Bs[am][ak + 0] = f2tf(v0.x); Bs[am][ak + 1] = f2tf(v0.y);
            Bs[am][ak + 2] = f2tf(v0.z); Bs[am][ak + 3] = f2tf(v0.w);
            Bs[am][ak + 4] = f2tf(v1.x); Bs[am][ak + 5] = f2tf(v1.y);
            Bs[am][ak + 6] = f2tf(v1.z); Bs[am][ak + 7] = f2tf(v1.w);
        }
        __syncthreads();
        #pragma unroll
        for (int ks = 0; ks < 4; ks++) {
            const int kk = ks * 8;
            unsigned a[2][4], bf[2][2];
            #pragma unroll
            for (int mi = 0; mi < 2; mi++) {
                const int mr = m0 + mi * 16;
                a[mi][0] = As[mr + g][kk + t4];
                a[mi][1] = As[mr + g + 8][kk + t4];
                a[mi][2] = As[mr + g][kk + t4 + 4];
                a[mi][3] = As[mr + g + 8][kk + t4 + 4];
            }
            #pragma unroll
            for (int ni = 0; ni < 2; ni++) {
                const int nc = n0 + ni * 8 + g;
                bf[ni][0] = Bs[nc][kk + t4];
                bf[ni][1] = Bs[nc][kk + t4 + 4];
            }
            #pragma unroll
            for (int mi = 0; mi < 2; mi++)
                #pragma unroll
                for (int ni = 0; ni < 2; ni++)
                    mma8(acc[mi][ni], a[mi], bf[ni]);
        }
        __syncthreads();
    }

    #pragma unroll
    for (int mi = 0; mi < 2; mi++) {
        const int ol = row0 + m0 + mi * 16 + g;
        const int oh = ol + 8;
        const float bl = pb[ol], bh = pb[oh];
        float* basel = out + ((size_t)b * CDIM + ol) * HW;
        float* baseh = out + ((size_t)b * CDIM + oh) * HW;
        #pragma unroll
        for (int ni = 0; ni < 2; ni++) {
            const int p = col0 + n0 + ni * 8 + 2 * t4;
            *(float2*)(basel + p) =
                make_float2(acc[mi][ni][0] + bl, acc[mi][ni][1] + bl);
            *(float2*)(baseh + p) =
                make_float2(acc[mi][ni][2] + bh, acc[mi][ni][3] + bh);
        }
    }
}

// ---------------------------------------------------------------------------
extern "C" void kernel_launch(void* const* d_in, const int* in_sizes, int n_in,
                              void* d_out, int out_size)
{
    const float* x   = (const float*)d_in[0];
    const float* w0  = (const float*)d_in[1];
    const float* bb0 = (const float*)d_in[2];
    const float* w1  = (const float*)d_in[3];
    const float* bb1 = (const float*)d_in[4];
    const float* w2  = (const float*)d_in[5];
    const float* bb2 = (const float*)d_in[6];
    const float* pw  = (const float*)d_in[7];
    const float* pb  = (const float*)d_in[8];
    float* out = (float*)d_out;

    qkv_gemm_kernel<<<dim3(HW / 64, 768 / 64, BATCH), 256>>>(
        x, w0, bb0, w1, bb1, w2, bb2);

    attn_kernel<<<(BATCH * NH * HW / 4) / 8, 256>>>();

    proj_gemm_kernel<<<dim3(HW / 64, CDIM / 64, BATCH), 256>>>(pw, pb, out);
}